// round 11
// baseline (speedup 1.0000x reference)
#include <cuda_runtime.h>
#include <math.h>

#define NB 32
#define NS 1024
#define ND 256
#define NDS 64
#define NM 3
#define TS 128   // timesteps per out_kernel block

typedef unsigned long long ull;

// ---------------- scratch (device globals; no cudaMalloc allowed) ----------
__device__ float g_xp[(size_t)NB * NS * NM * NDS];   // [B][S][M*DS]  (XW@x + Xb + Hb)
__device__ float g_hn[(size_t)NB * NS * NM * NDS];   // [B][S][M*DS]  (h_new per step)

// ---------------- packed f32x2 helpers -------------------------------------
__device__ __forceinline__ void fma2(ull& acc, ull a, ull b) {
    asm("fma.rn.f32x2 %0, %1, %2, %0;" : "+l"(acc) : "l"(a), "l"(b));
}
__device__ __forceinline__ ull pack2(float x, float y) {
    ull r; asm("mov.b64 %0, {%1, %2};" : "=l"(r) : "f"(x), "f"(y)); return r;
}
__device__ __forceinline__ float2 unpack2(ull v) {
    float2 r; asm("mov.b64 {%0, %1}, %2;" : "=f"(r.x), "=f"(r.y) : "l"(v)); return r;
}
__device__ __forceinline__ float sum2(ull v) { float2 f = unpack2(v); return f.x + f.y; }

__device__ __forceinline__ float tanh_fast(float x) {
    float y; asm("tanh.approx.f32 %0, %1;" : "=f"(y) : "f"(x)); return y;
}

// ---------------- cp.async helpers ------------------------------------------
__device__ __forceinline__ void cp_async16(void* smem_dst, const void* gsrc) {
    unsigned s = (unsigned)__cvta_generic_to_shared(smem_dst);
    asm volatile("cp.async.ca.shared.global [%0], [%1], 16;" :: "r"(s), "l"(gsrc));
}
__device__ __forceinline__ void cp_commit() { asm volatile("cp.async.commit_group;"); }
__device__ __forceinline__ void cp_wait1()  { asm volatile("cp.async.wait_group 1;"); }

// ======================= Kernel 1: xp = XW@x + Xb + Hb =====================
// (unchanged from the 1585us baseline)
__global__ void __launch_bounds__(256) xproj_kernel(
    const float* __restrict__ xa, const float* __restrict__ xv, const float* __restrict__ xl,
    const float* __restrict__ XW, const float* __restrict__ Xb, const float* __restrict__ Hb)
{
    __shared__ __align__(16) float Xs[64][64];   // [t][k]
    __shared__ __align__(16) float Wt[64][64];   // [k][d] (XW transposed)

    const int m  = blockIdx.z;
    const int bb = blockIdx.y;
    const int t0 = blockIdx.x * 64;
    const float* xm = (m == 0) ? xa : ((m == 1) ? xv : xl);

    const int tid = threadIdx.x;
    const int tx = tid & 15, ty = tid >> 4;

    ull acc[4][2] = {};

    const int ldx_row = tid >> 2, ldx_q = tid & 3;
    const int ldw_d = tid & 63, ldw_g = tid >> 6;

    for (int kc = 0; kc < 4; kc++) {
        __syncthreads();
        #pragma unroll
        for (int g = 0; g < 4; g++) {
            int col = ldx_q * 16 + g * 4;
            float4 v = *(const float4*)&xm[((size_t)(bb * NS) + t0 + ldx_row) * ND + kc * 64 + col];
            *(float4*)&Xs[ldx_row][col] = v;
        }
        #pragma unroll
        for (int g = 0; g < 4; g++) {
            int kk = ldw_g * 16 + g * 4;
            float4 w = *(const float4*)&XW[((size_t)(m * NDS + ldw_d)) * ND + kc * 64 + kk];
            Wt[kk + 0][ldw_d] = w.x; Wt[kk + 1][ldw_d] = w.y;
            Wt[kk + 2][ldw_d] = w.z; Wt[kk + 3][ldw_d] = w.w;
        }
        __syncthreads();
        #pragma unroll 16
        for (int kk = 0; kk < 64; kk++) {
            ull bv0 = *(const ull*)&Wt[kk][2 * tx];
            ull bv1 = *(const ull*)&Wt[kk][2 * tx + 32];
            #pragma unroll
            for (int i = 0; i < 4; i++) {
                float a = Xs[ty + 16 * i][kk];
                ull aa = pack2(a, a);
                fma2(acc[i][0], aa, bv0);
                fma2(acc[i][1], aa, bv1);
            }
        }
    }
    #pragma unroll
    for (int i = 0; i < 4; i++) {
        #pragma unroll
        for (int jp = 0; jp < 2; jp++) {
            int d0 = 2 * tx + 32 * jp;
            float2 v = unpack2(acc[i][jp]);
            float2 xb = *(const float2*)&Xb[m * NDS + d0];
            float2 hb = *(const float2*)&Hb[m * NDS + d0];
            v.x += xb.x + hb.x;
            v.y += xb.y + hb.y;
            *(float2*)&g_xp[((size_t)(bb * NS) + t0 + ty + 16 * i) * (NM * NDS) + m * NDS + d0] = v;
        }
    }
}

// ======================= Kernel 2: sequential scan =========================
// grid = 32 (one block per batch element), 384 threads, uniform control flow.
// Per step: TWO __syncthreads only.
//   stage A: all threads compute z-partials (W1) -> sh_part        [sync]
//   stage B: every warp redundantly finishes the gating chain
//            (reduce + tanh + W2 row for its m4 + 15-shfl tree + softmax)
//            interleaved with its own HW/CW dots; combine, silu    [sync]
__global__ void __launch_bounds__(384, 1) scan_kernel(
    const float* __restrict__ W1, const float* __restrict__ b1,
    const float* __restrict__ W2, const float* __restrict__ b2,
    const float* __restrict__ HW, const float* __restrict__ CW)
{
    __shared__ __align__(16) float sh_h[2][NM * NDS];   // double-buffered state
    __shared__ __align__(16) float sh_part[6][NDS];     // z-partials [seg][o]

    const int u  = threadIdx.x;
    const int bb = blockIdx.x;
    const int lane = u & 31;

    // phase-1 mapping
    const int o1  = u & 63;
    const int seg = u >> 6;            // 0..5
    // phase-2 mapping (pairs): o2 = m*64+d, half selects elems [h*32, h*32+32)
    const int half = u & 1;
    const int o2   = u >> 1;           // 0..191
    const int m4   = o2 >> 6;          // warp-uniform (o2 spans 16 values)
    const int s1 = (m4 == 0) ? 1 : 0;  // in {0,1}
    const int s2 = (m4 == 2) ? 1 : 2;  // in {1,2}

    // ---- register weights ----
    ull whw[16];   // HW[m4][d4][half*32 .. +32)
    #pragma unroll
    for (int j = 0; j < 16; j++)
        whw[j] = *(const ull*)(HW + (size_t)o2 * NDS + half * 32 + 2 * j);

    ull wc1[16];   // CW[m4][s1][d4][half*32 .. +32)
    #pragma unroll
    for (int j = 0; j < 16; j++)
        wc1[j] = *(const ull*)(CW + ((size_t)((m4 * NM + s1) * NDS + (o2 & 63))) * NDS + half * 32 + 2 * j);

    ull wc2[16];   // CW[m4][s2][d4][half*32 .. +32)
    #pragma unroll
    for (int j = 0; j < 16; j++)
        wc2[j] = *(const ull*)(CW + ((size_t)((m4 * NM + s2) * NDS + (o2 & 63))) * NDS + half * 32 + 2 * j);

    // gating per-lane constants: lane owns z[2*lane], z[2*lane+1];
    // this warp only ever needs attention row m4.
    ull w2r[3];
    #pragma unroll
    for (int j = 0; j < 3; j++)
        w2r[j] = *(const ull*)(W2 + (size_t)(3 * m4 + j) * NDS + 2 * lane);
    const float2 b1r = *(const float2*)(b1 + 2 * lane);
    const float b2r0 = b2[3 * m4 + 0], b2r1 = b2[3 * m4 + 1], b2r2 = b2[3 * m4 + 2];

    // W1 row pointer: read through L1 each step (48KB, L1-resident)
    const ulonglong2* __restrict__ w1p =
        (const ulonglong2*)(W1 + (size_t)o1 * (NM * NDS) + seg * 32);

    const float* xp_base = g_xp + (size_t)bb * NS * (NM * NDS) + o2;
    float* hn_base = g_hn + (size_t)bb * NS * (NM * NDS) + o2;
    float xp_c = (half == 0) ? __ldg(xp_base) : 0.0f;

    if (u < NM * NDS) sh_h[0][u] = 0.0f;
    __syncthreads();

    for (int t = 0; t < NS; t++) {
        const int cur = t & 1;
        const float* hbuf = &sh_h[cur][0];

        // prefetch next xp (even threads only)
        float xp_n = 0.0f;
        if (half == 0) {
            int tn = (t + 1 < NS) ? (t + 1) : t;
            xp_n = __ldg(xp_base + (size_t)tn * (NM * NDS));
        }

        // ---- stage A: z-partials ----
        {
            const float* hseg = hbuf + seg * 32;
            ull a0 = 0, a1 = 0;
            #pragma unroll
            for (int j = 0; j < 8; j++) {
                ulonglong2 hv = *(const ulonglong2*)(hseg + 4 * j);
                ulonglong2 wv = w1p[j];
                fma2(a0, hv.x, wv.x);
                fma2(a1, hv.y, wv.y);
            }
            sh_part[seg][o1] = sum2(a0) + sum2(a1);
        }
        __syncthreads();

        // ---- stage B: gating chain (long latency, starts first) ----
        float2 zv = b1r;
        #pragma unroll
        for (int s = 0; s < 6; s++) {
            float2 pp = *(const float2*)&sh_part[s][2 * lane];
            zv.x += pp.x; zv.y += pp.y;
        }
        ull zp = pack2(tanh_fast(zv.x), tanh_fast(zv.y));
        ull q0 = 0, q1 = 0, q2 = 0;
        fma2(q0, zp, w2r[0]); fma2(q1, zp, w2r[1]); fma2(q2, zp, w2r[2]);
        float r0 = sum2(q0), r1 = sum2(q1), r2 = sum2(q2);
        #pragma unroll
        for (int off = 16; off; off >>= 1) {
            r0 += __shfl_xor_sync(0xffffffffu, r0, off);
            r1 += __shfl_xor_sync(0xffffffffu, r1, off);
            r2 += __shfl_xor_sync(0xffffffffu, r2, off);
        }

        // ---- stage B: HW + CW dots (overlap the gating latency) ----
        const float* hm = hbuf + m4 * 64 + half * 32;
        const float* h1 = hbuf + s1 * 64 + half * 32;
        const float* h2 = hbuf + s2 * 64 + half * 32;
        ull dh0 = 0, dh1 = 0, dc10 = 0, dc11 = 0, dc20 = 0, dc21 = 0;
        #pragma unroll
        for (int j = 0; j < 8; j++) {
            ulonglong2 hv = *(const ulonglong2*)(hm + 4 * j);
            fma2(dh0, hv.x, whw[2 * j]);
            fma2(dh1, hv.y, whw[2 * j + 1]);
        }
        #pragma unroll
        for (int j = 0; j < 8; j++) {
            ulonglong2 hv = *(const ulonglong2*)(h1 + 4 * j);
            fma2(dc10, hv.x, wc1[2 * j]);
            fma2(dc11, hv.y, wc1[2 * j + 1]);
        }
        #pragma unroll
        for (int j = 0; j < 8; j++) {
            ulonglong2 hv = *(const ulonglong2*)(h2 + 4 * j);
            fma2(dc20, hv.x, wc2[2 * j]);
            fma2(dc21, hv.y, wc2[2 * j + 1]);
        }

        // softmax over row m4 (mask applied after softmax; diagonal stays in
        // the denominator but is never used since s1,s2 != m4)
        float e0 = __expf(r0 + b2r0), e1 = __expf(r1 + b2r1), e2 = __expf(r2 + b2r2);
        float inv = __frcp_rn(e0 + e1 + e2);
        float a1f = ((s1 == 0) ? e0 : e1) * inv;
        float a2f = ((s2 == 1) ? e1 : e2) * inv;

        float val = sum2(dh0) + sum2(dh1)
                  + a1f * (sum2(dc10) + sum2(dc11))
                  + a2f * (sum2(dc20) + sum2(dc21));
        val += __shfl_xor_sync(0xffffffffu, val, 1);   // combine halves

        if (half == 0) {
            float su = val + xp_c;
            float hn = su / (1.0f + __expf(-su));       // silu
            sh_h[cur ^ 1][o2] = hn;
            hn_base[(size_t)t * (NM * NDS)] = hn;
        }
        xp_c = xp_n;
        __syncthreads();
    }
}

// ======================= Kernel 3: y = OW@h_new + Ob; out = LN(y + x) ======
// (unchanged from the 1585us baseline)
__global__ void __launch_bounds__(256) out_kernel(
    const float* __restrict__ xa, const float* __restrict__ xv, const float* __restrict__ xl,
    const float* __restrict__ OW, const float* __restrict__ Ob,
    const float* __restrict__ lng, const float* __restrict__ lnb,
    float* __restrict__ out)
{
    __shared__ __align__(16) float sh_ht[2][8][NDS];
    __shared__ float sh_red[2][8][2];

    const int tid = threadIdx.x;
    const int t0  = blockIdx.x * TS;
    const int bb  = blockIdx.y;
    const int m   = blockIdx.z;
    const float* xm = (m == 0) ? xa : ((m == 1) ? xv : xl);

    ull ow[32];
    #pragma unroll
    for (int j = 0; j < 32; j++)
        ow[j] = *(const ull*)(OW + ((size_t)m * ND + tid) * NDS + 2 * j);
    const float ob = Ob[m * ND + tid];
    const float gg = lng[m * ND + tid];
    const float be = lnb[m * ND + tid];

    const float* hn_base = g_hn + ((size_t)(bb * NS + t0)) * (NM * NDS) + m * NDS;
    const float* x_base  = xm + ((size_t)bb * NS + t0) * ND;
    float* o_base = out + ((size_t)m * NB + bb) * (size_t)NS * ND + (size_t)t0 * ND;

    const int ptt = tid >> 4;
    const int pq  = tid & 15;

    if (tid < 128) {
        int tc = min(0 * 8 + ptt, TS - 1);
        cp_async16(&sh_ht[0][ptt][pq * 4], hn_base + (size_t)tc * (NM * NDS) + pq * 4);
    }
    cp_commit();

    const int NG = TS / 8;
    for (int g = 0; g < NG; g++) {
        const int buf = g & 1;
        if (tid < 128) {
            int tc = min((g + 1) * 8 + ptt, TS - 1);
            cp_async16(&sh_ht[buf ^ 1][ptt][pq * 4], hn_base + (size_t)tc * (NM * NDS) + pq * 4);
        }
        cp_commit();
        cp_wait1();
        __syncthreads();

        #pragma unroll
        for (int k = 0; k < 8; k++) {
            const int t = g * 8 + k;
            float xval = __ldg(x_base + (size_t)t * ND + tid);

            ull acc = 0;
            #pragma unroll
            for (int j = 0; j < 32; j++)
                fma2(acc, *(const ull*)&sh_ht[buf][k][2 * j], ow[j]);
            float v = sum2(acc) + ob + xval;

            float s = v, ss = v * v;
            #pragma unroll
            for (int off = 16; off; off >>= 1) {
                s  += __shfl_xor_sync(0xffffffffu, s, off);
                ss += __shfl_xor_sync(0xffffffffu, ss, off);
            }
            const int w = tid >> 5, lw = tid & 31;
            const int rb = t & 1;
            if (lw == 0) { sh_red[rb][w][0] = s; sh_red[rb][w][1] = ss; }
            __syncthreads();
            float S = 0.0f, SS = 0.0f;
            #pragma unroll
            for (int w2 = 0; w2 < 8; w2++) { S += sh_red[rb][w2][0]; SS += sh_red[rb][w2][1]; }
            float mu  = S * (1.0f / 256.0f);
            float var = SS * (1.0f / 256.0f) - mu * mu;
            float r   = rsqrtf(var + 1e-5f);
            o_base[(size_t)t * ND + tid] = (v - mu) * r * gg + be;
        }
    }
}

// =============================== launch ====================================
extern "C" void kernel_launch(void* const* d_in, const int* in_sizes, int n_in,
                              void* d_out, int out_size) {
    const float* xa  = (const float*)d_in[0];
    const float* xv  = (const float*)d_in[1];
    const float* xl  = (const float*)d_in[2];
    const float* XW  = (const float*)d_in[3];
    const float* Xb  = (const float*)d_in[4];
    const float* HW  = (const float*)d_in[5];
    const float* Hb  = (const float*)d_in[6];
    const float* OW  = (const float*)d_in[7];
    const float* Ob  = (const float*)d_in[8];
    const float* CW  = (const float*)d_in[9];
    const float* W1  = (const float*)d_in[10];
    const float* b1  = (const float*)d_in[11];
    const float* W2  = (const float*)d_in[12];
    const float* b2  = (const float*)d_in[13];
    const float* lng = (const float*)d_in[14];
    const float* lnb = (const float*)d_in[15];
    float* out = (float*)d_out;

    dim3 gA(NS / 64, NB, NM);
    xproj_kernel<<<gA, 256>>>(xa, xv, xl, XW, Xb, Hb);

    scan_kernel<<<NB, 384>>>(W1, b1, W2, b2, HW, CW);

    dim3 gC(NS / TS, NB, NM);
    out_kernel<<<gC, 256>>>(xa, xv, xl, OW, Ob, lng, lnb, out);
}

// round 12
// speedup vs baseline: 1.8839x; 1.8839x over previous
#include <cuda_runtime.h>
#include <math.h>

#define NB 32
#define NS 1024
#define ND 256
#define NDS 64
#define NM 3
#define TS 128   // timesteps per out_kernel block

typedef unsigned long long ull;

// ---------------- scratch (device globals; no cudaMalloc allowed) ----------
__device__ float g_xp[(size_t)NB * NS * NM * NDS];   // [B][S][M*DS]  (XW@x + Xb + Hb)
__device__ float g_hn[(size_t)NB * NS * NM * NDS];   // [B][S][M*DS]  (h_new per step)

// ---------------- packed f32x2 helpers -------------------------------------
__device__ __forceinline__ void fma2(ull& acc, ull a, ull b) {
    asm("fma.rn.f32x2 %0, %1, %2, %0;" : "+l"(acc) : "l"(a), "l"(b));
}
__device__ __forceinline__ ull pack2(float x, float y) {
    ull r; asm("mov.b64 %0, {%1, %2};" : "=l"(r) : "f"(x), "f"(y)); return r;
}
__device__ __forceinline__ float2 unpack2(ull v) {
    float2 r; asm("mov.b64 {%0, %1}, %2;" : "=f"(r.x), "=f"(r.y) : "l"(v)); return r;
}
__device__ __forceinline__ float sum2(ull v) { float2 f = unpack2(v); return f.x + f.y; }

__device__ __forceinline__ float tanh_fast(float x) {
    float y; asm("tanh.approx.f32 %0, %1;" : "=f"(y) : "f"(x)); return y;
}

// ---------------- cp.async helpers ------------------------------------------
__device__ __forceinline__ void cp_async16(void* smem_dst, const void* gsrc) {
    unsigned s = (unsigned)__cvta_generic_to_shared(smem_dst);
    asm volatile("cp.async.ca.shared.global [%0], [%1], 16;" :: "r"(s), "l"(gsrc));
}
__device__ __forceinline__ void cp_commit() { asm volatile("cp.async.commit_group;"); }
__device__ __forceinline__ void cp_wait1()  { asm volatile("cp.async.wait_group 1;"); }

// ======================= Kernel 1: xp = XW@x + Xb + Hb =====================
// (unchanged from the 1585us baseline)
__global__ void __launch_bounds__(256) xproj_kernel(
    const float* __restrict__ xa, const float* __restrict__ xv, const float* __restrict__ xl,
    const float* __restrict__ XW, const float* __restrict__ Xb, const float* __restrict__ Hb)
{
    __shared__ __align__(16) float Xs[64][64];   // [t][k]
    __shared__ __align__(16) float Wt[64][64];   // [k][d] (XW transposed)

    const int m  = blockIdx.z;
    const int bb = blockIdx.y;
    const int t0 = blockIdx.x * 64;
    const float* xm = (m == 0) ? xa : ((m == 1) ? xv : xl);

    const int tid = threadIdx.x;
    const int tx = tid & 15, ty = tid >> 4;

    ull acc[4][2] = {};

    const int ldx_row = tid >> 2, ldx_q = tid & 3;
    const int ldw_d = tid & 63, ldw_g = tid >> 6;

    for (int kc = 0; kc < 4; kc++) {
        __syncthreads();
        #pragma unroll
        for (int g = 0; g < 4; g++) {
            int col = ldx_q * 16 + g * 4;
            float4 v = *(const float4*)&xm[((size_t)(bb * NS) + t0 + ldx_row) * ND + kc * 64 + col];
            *(float4*)&Xs[ldx_row][col] = v;
        }
        #pragma unroll
        for (int g = 0; g < 4; g++) {
            int kk = ldw_g * 16 + g * 4;
            float4 w = *(const float4*)&XW[((size_t)(m * NDS + ldw_d)) * ND + kc * 64 + kk];
            Wt[kk + 0][ldw_d] = w.x; Wt[kk + 1][ldw_d] = w.y;
            Wt[kk + 2][ldw_d] = w.z; Wt[kk + 3][ldw_d] = w.w;
        }
        __syncthreads();
        #pragma unroll 16
        for (int kk = 0; kk < 64; kk++) {
            ull bv0 = *(const ull*)&Wt[kk][2 * tx];
            ull bv1 = *(const ull*)&Wt[kk][2 * tx + 32];
            #pragma unroll
            for (int i = 0; i < 4; i++) {
                float a = Xs[ty + 16 * i][kk];
                ull aa = pack2(a, a);
                fma2(acc[i][0], aa, bv0);
                fma2(acc[i][1], aa, bv1);
            }
        }
    }
    #pragma unroll
    for (int i = 0; i < 4; i++) {
        #pragma unroll
        for (int jp = 0; jp < 2; jp++) {
            int d0 = 2 * tx + 32 * jp;
            float2 v = unpack2(acc[i][jp]);
            float2 xb = *(const float2*)&Xb[m * NDS + d0];
            float2 hb = *(const float2*)&Hb[m * NDS + d0];
            v.x += xb.x + hb.x;
            v.y += xb.y + hb.y;
            *(float2*)&g_xp[((size_t)(bb * NS) + t0 + ty + 16 * i) * (NM * NDS) + m * NDS + d0] = v;
        }
    }
}

// ======================= Kernel 2: the sequential scan =====================
// R8 (1585us) skeleton, 384 threads, block-wide syncs, weights in registers.
// Changes vs R8: tanh.approx instead of tanhf; tanh fused into the W2 stage;
// softmax fused into phase 4.  Per step: THREE __syncthreads (was five).
__global__ void __launch_bounds__(384, 1) scan_kernel(
    const float* __restrict__ W1, const float* __restrict__ b1,
    const float* __restrict__ W2, const float* __restrict__ b2,
    const float* __restrict__ HW, const float* __restrict__ CW)
{
    __shared__ __align__(16) float sh_h[2][NM][NDS];  // double-buffered state
    __shared__ float sh_part[6][NDS];
    __shared__ float sh_raw[12];

    const int u  = threadIdx.x;
    const int bb = blockIdx.x;
    const int lane = u & 31;
    const int wp   = u >> 5;          // warp id 0..11

    // phase-1 mapping: output o1 (0..63), hc segment seg (0..5) of 32 elems
    const int o1  = u & 63;
    const int seg = u >> 6;
    // phase-4 mapping: output o2 = m*64+d (0..191), dot-half (0/1)
    const int half = u & 1;
    const int o2   = u >> 1;
    const int m4   = o2 >> 6;
    const int d4   = o2 & 63;
    const int s1 = (m4 == 0) ? 1 : 0;
    const int s2 = (m4 == 2) ? 1 : 2;
    const int src = half ? s2 : s1;

    // ---- weights into registers (packed f32 pairs) — same set as R8 ----
    ull w1r[16];
    #pragma unroll
    for (int j = 0; j < 16; j++)
        w1r[j] = *(const ull*)(W1 + o1 * (NM * NDS) + seg * 32 + 2 * j);

    ull whw[16];   // HW[m4][d4][half*32 .. half*32+32)
    #pragma unroll
    for (int j = 0; j < 16; j++)
        whw[j] = *(const ull*)(HW + ((size_t)(m4 * NDS + d4)) * NDS + half * 32 + 2 * j);

    ull wcw[32];   // CW[m4][src][d4][0..64)
    #pragma unroll
    for (int j = 0; j < 32; j++)
        wcw[j] = *(const ull*)(CW + ((size_t)((m4 * NM + src) * NDS + d4)) * NDS + 2 * j);

    // gating constants (small): lane owns z[2*lane..2*lane+1]
    const float2 b1r = *(const float2*)(b1 + 2 * lane);
    ull w2l = 0;                      // W2[wp][2*lane..2*lane+1] for warps 0..8
    float b2p = 0.0f;
    if (wp < 9) {
        w2l = *(const ull*)(W2 + (size_t)wp * NDS + 2 * lane);
        b2p = b2[wp];
    }
    // phase-4 softmax constant: which raw element this thread scales by
    // (raw values come from sh_raw; b2 already folded in there)

    if (u < NM * NDS) (&sh_h[0][0][0])[u] = 0.0f;
    __syncthreads();

    const float* xp_base = g_xp + (size_t)bb * NS * (NM * NDS);
    float xp_c = __ldg(xp_base + o2);      // t = 0

    for (int t = 0; t < NS; t++) {
        const int cur = t & 1, nxt = cur ^ 1;
        const int tn = (t + 1 < NS) ? (t + 1) : t;
        float xp_n = __ldg(xp_base + (size_t)tn * (NM * NDS) + o2);  // prefetch

        // ---- phase 1: z-partials: W1 row o1, segment seg of hc ----
        const float* hseg = &sh_h[cur][0][0] + seg * 32;
        ull a1 = 0, a2 = 0;
        #pragma unroll
        for (int j = 0; j < 8; j++) {
            ulonglong2 hv = *(const ulonglong2*)(hseg + 4 * j);
            fma2(a1, hv.x, w1r[2 * j]);
            fma2(a2, hv.y, w1r[2 * j + 1]);
        }
        sh_part[seg][o1] = sum2(a1) + sum2(a2);
        __syncthreads();

        // ---- fused z + W2 stage: warps 0..8; each lane rebuilds its z pair ----
        if (wp < 9) {
            float2 zv = b1r;
            #pragma unroll
            for (int s = 0; s < 6; s++) {
                float2 pp = *(const float2*)&sh_part[s][2 * lane];
                zv.x += pp.x; zv.y += pp.y;
            }
            ull zp = pack2(tanh_fast(zv.x), tanh_fast(zv.y));
            ull q = 0; fma2(q, zp, w2l);
            float pr = sum2(q);
            #pragma unroll
            for (int off = 16; off; off >>= 1)
                pr += __shfl_down_sync(0xffffffffu, pr, off);
            if (lane == 0) sh_raw[wp] = pr + b2p;
        }
        __syncthreads();

        // ---- phase 4: inline softmax + HW.h + coupling + xp; silu ----
        float r0 = sh_raw[m4 * 3 + 0];
        float r1 = sh_raw[m4 * 3 + 1];
        float r2 = sh_raw[m4 * 3 + 2];
        float e0 = __expf(r0), e1 = __expf(r1), e2 = __expf(r2);
        float inv = __frcp_rn(e0 + e1 + e2);
        float esrc = (src == 0) ? e0 : ((src == 1) ? e1 : e2);
        float a = esrc * inv;          // masked row: src != m4 always

        const float* hm = &sh_h[cur][m4][0] + half * 32;
        const float* hs = &sh_h[cur][src][0];
        ull ah0 = 0, ah1 = 0, c0 = 0, c1 = 0, c2 = 0, c3 = 0;
        #pragma unroll
        for (int j = 0; j < 8; j++) {
            ulonglong2 hv = *(const ulonglong2*)(hm + 4 * j);
            fma2(ah0, hv.x, whw[2 * j]);
            fma2(ah1, hv.y, whw[2 * j + 1]);
        }
        #pragma unroll
        for (int j = 0; j < 16; j++) {
            ulonglong2 hv = *(const ulonglong2*)(hs + 4 * j);
            if (j & 1) { fma2(c2, hv.x, wcw[2 * j]); fma2(c3, hv.y, wcw[2 * j + 1]); }
            else       { fma2(c0, hv.x, wcw[2 * j]); fma2(c1, hv.y, wcw[2 * j + 1]); }
        }

        float val = sum2(ah0) + sum2(ah1)
                  + a * (sum2(c0) + sum2(c1) + sum2(c2) + sum2(c3));
        val += __shfl_xor_sync(0xffffffffu, val, 1);   // combine halves
        if (half == 0) {
            float su = val + xp_c;
            float hn = su / (1.0f + __expf(-su));       // silu
            sh_h[nxt][m4][d4] = hn;
            g_hn[((size_t)(bb * NS + t)) * (NM * NDS) + o2] = hn;
        }
        xp_c = xp_n;
        __syncthreads();
    }
}

// ======================= Kernel 3: y = OW@h_new + Ob; out = LN(y + x) ======
// (unchanged from the 1585us baseline)
__global__ void __launch_bounds__(256) out_kernel(
    const float* __restrict__ xa, const float* __restrict__ xv, const float* __restrict__ xl,
    const float* __restrict__ OW, const float* __restrict__ Ob,
    const float* __restrict__ lng, const float* __restrict__ lnb,
    float* __restrict__ out)
{
    __shared__ __align__(16) float sh_ht[2][8][NDS];
    __shared__ float sh_red[2][8][2];

    const int tid = threadIdx.x;
    const int t0  = blockIdx.x * TS;
    const int bb  = blockIdx.y;
    const int m   = blockIdx.z;
    const float* xm = (m == 0) ? xa : ((m == 1) ? xv : xl);

    ull ow[32];
    #pragma unroll
    for (int j = 0; j < 32; j++)
        ow[j] = *(const ull*)(OW + ((size_t)m * ND + tid) * NDS + 2 * j);
    const float ob = Ob[m * ND + tid];
    const float gg = lng[m * ND + tid];
    const float be = lnb[m * ND + tid];

    const float* hn_base = g_hn + ((size_t)(bb * NS + t0)) * (NM * NDS) + m * NDS;
    const float* x_base  = xm + ((size_t)bb * NS + t0) * ND;
    float* o_base = out + ((size_t)m * NB + bb) * (size_t)NS * ND + (size_t)t0 * ND;

    const int ptt = tid >> 4;
    const int pq  = tid & 15;

    if (tid < 128) {
        int tc = min(0 * 8 + ptt, TS - 1);
        cp_async16(&sh_ht[0][ptt][pq * 4], hn_base + (size_t)tc * (NM * NDS) + pq * 4);
    }
    cp_commit();

    const int NG = TS / 8;
    for (int g = 0; g < NG; g++) {
        const int buf = g & 1;
        if (tid < 128) {
            int tc = min((g + 1) * 8 + ptt, TS - 1);
            cp_async16(&sh_ht[buf ^ 1][ptt][pq * 4], hn_base + (size_t)tc * (NM * NDS) + pq * 4);
        }
        cp_commit();
        cp_wait1();
        __syncthreads();

        #pragma unroll
        for (int k = 0; k < 8; k++) {
            const int t = g * 8 + k;
            float xval = __ldg(x_base + (size_t)t * ND + tid);

            ull acc = 0;
            #pragma unroll
            for (int j = 0; j < 32; j++)
                fma2(acc, *(const ull*)&sh_ht[buf][k][2 * j], ow[j]);
            float v = sum2(acc) + ob + xval;

            float s = v, ss = v * v;
            #pragma unroll
            for (int off = 16; off; off >>= 1) {
                s  += __shfl_xor_sync(0xffffffffu, s, off);
                ss += __shfl_xor_sync(0xffffffffu, ss, off);
            }
            const int w = tid >> 5, lw = tid & 31;
            const int rb = t & 1;
            if (lw == 0) { sh_red[rb][w][0] = s; sh_red[rb][w][1] = ss; }
            __syncthreads();
            float S = 0.0f, SS = 0.0f;
            #pragma unroll
            for (int w2 = 0; w2 < 8; w2++) { S += sh_red[rb][w2][0]; SS += sh_red[rb][w2][1]; }
            float mu  = S * (1.0f / 256.0f);
            float var = SS * (1.0f / 256.0f) - mu * mu;
            float r   = rsqrtf(var + 1e-5f);
            o_base[(size_t)t * ND + tid] = (v - mu) * r * gg + be;
        }
    }
}

// =============================== launch ====================================
extern "C" void kernel_launch(void* const* d_in, const int* in_sizes, int n_in,
                              void* d_out, int out_size) {
    const float* xa  = (const float*)d_in[0];
    const float* xv  = (const float*)d_in[1];
    const float* xl  = (const float*)d_in[2];
    const float* XW  = (const float*)d_in[3];
    const float* Xb  = (const float*)d_in[4];
    const float* HW  = (const float*)d_in[5];
    const float* Hb  = (const float*)d_in[6];
    const float* OW  = (const float*)d_in[7];
    const float* Ob  = (const float*)d_in[8];
    const float* CW  = (const float*)d_in[9];
    const float* W1  = (const float*)d_in[10];
    const float* b1  = (const float*)d_in[11];
    const float* W2  = (const float*)d_in[12];
    const float* b2  = (const float*)d_in[13];
    const float* lng = (const float*)d_in[14];
    const float* lnb = (const float*)d_in[15];
    float* out = (float*)d_out;

    dim3 gA(NS / 64, NB, NM);
    xproj_kernel<<<gA, 256>>>(xa, xv, xl, XW, Xb, Hb);

    scan_kernel<<<NB, 384>>>(W1, b1, W2, b2, HW, CW);

    dim3 gC(NS / TS, NB, NM);
    out_kernel<<<gC, 256>>>(xa, xv, xl, OW, Ob, lng, lnb, out);
}